// round 9
// baseline (speedup 1.0000x reference)
#include <cuda_runtime.h>
#include <math.h>
#include <stdint.h>

#define NT 256
#define ROWS 16
#define L 336
#define OFF_MU (1024*96*7)
#define OFF_LV (OFF_MU + 7168*64)
#define OFF_LD (OFF_LV + 7168*64)

// smem pool layout (floats)
#define P_A     0        // xn[16][336]; aliases: sINP[16][192], r2chunk[16][256], recon[16][96]
#define P_PB    5376     // pbar[16][16]
#define P_MEAN  5632
#define P_STD   5648
#define P_SCALE 5664
#define P_B     5680     // ml[16][128] / r1[16][256]  (4096)
#define P_WT    9776     // weight tiles: large 2 x [8][516] = 8256 (small uses 2 x [8][260] subset)
#define SMEM_FLOATS 18096
#define SMEM_BYTES (SMEM_FLOATS*4)

// k-pair-interleaved weights: layout [k/2][m][2] — element (k,m) at ((k>>1)*M + m)*2 + (k&1)
__device__ __align__(16) float g_Wsct[336*128];   // K=336, M=128 (m padded 96->128)
__device__ __align__(16) float g_Wr3t[512*128];   // K=512, M=128
__device__ __align__(16) float g_Wmlt[128*128];   // K=128, M=128 ([mu|lv])
__device__ __align__(16) float g_bml[128];
__device__ __align__(16) float g_Wct[16*128];     // K=16,  M=128
__device__ __align__(16) float g_bc[128];
__device__ __align__(16) float g_Wr1t[192*256];   // K=192, M=256
__device__ __align__(16) float g_Wr2t[256*512];   // K=256, M=512
__device__ double g_uhat[8*64];
__device__ double g_cflow[8];
__device__ __align__(16) float g_short[7168*96];  // shortcut scratch (gmem)

__global__ void prep_kernel(const float* __restrict__ W_sc,
                            const float* __restrict__ W_mu, const float* __restrict__ b_mu,
                            const float* __restrict__ W_lv, const float* __restrict__ b_lv,
                            const float* __restrict__ W_r3,
                            const float* __restrict__ W_fu, const float* __restrict__ b_fu,
                            const float* __restrict__ W_ts, const float* __restrict__ b_ts,
                            const float* __restrict__ flow_u, const float* __restrict__ flow_w,
                            const float* __restrict__ W_r1, const float* __restrict__ W_r2)
{
    int idx = blockIdx.x * blockDim.x + threadIdx.x;
    int stride = gridDim.x * blockDim.x;
    const int S0 = 336*128;          // Wsct
    const int S1 = S0 + 512*128;     // Wr3t
    const int S2 = S1 + 128*128;     // Wmlt
    const int S3 = S2 + 128;         // bml
    const int S4 = S3 + 16*128;      // Wct
    const int S5 = S4 + 128;         // bc
    const int S6 = S5 + 192*256;     // Wr1t
    const int S7 = S6 + 256*512;     // Wr2t
    const int S8 = S7 + 8;           // flows
    for (int i = idx; i < S8; i += stride) {
        if (i < S0) {
            int e = i & 1, m = (i >> 1) & 127, p = (i >> 1) >> 7;
            int k = 2*p + e;
            g_Wsct[i] = (m < 96) ? W_sc[m*336 + k] : 0.f;
        } else if (i < S1) {
            int j = i - S0;
            int e = j & 1, m = (j >> 1) & 127, p = (j >> 1) >> 7;
            int k = 2*p + e;
            g_Wr3t[j] = (m < 96) ? W_r3[m*512 + k] : 0.f;
        } else if (i < S2) {
            int j = i - S1;
            int e = j & 1, m = (j >> 1) & 127, p = (j >> 1) >> 7;
            int k = 2*p + e;
            g_Wmlt[j] = (m < 64) ? W_mu[m*128 + k] : W_lv[(m-64)*128 + k];
        } else if (i < S3) {
            int j = i - S2;
            g_bml[j] = (j < 64) ? b_mu[j] : b_lv[j-64];
        } else if (i < S4) {
            int j = i - S3;
            int e = j & 1, m = (j >> 1) & 127, p = (j >> 1) >> 7;
            int l = 2*p + e;
            float s = 0.f;
            for (int d = 0; d < 128; d++) s += W_fu[m*256 + d] * W_ts[d*16 + l];
            g_Wct[j] = s;
        } else if (i < S5) {
            int h = i - S4;
            float s = 0.f;
            for (int d = 0; d < 128; d++) s += W_fu[h*256 + d] * b_ts[d];
            g_bc[h] = s + b_fu[h];
        } else if (i < S6) {
            int j = i - S5;
            int e = j & 1, m = (j >> 1) & 255, p = (j >> 1) >> 8;
            int k = 2*p + e;
            g_Wr1t[j] = W_r1[m*192 + k];
        } else if (i < S7) {
            int j = i - S6;
            int e = j & 1, m = (j >> 1) & 511, p = (j >> 1) >> 9;
            int k = 2*p + e;
            g_Wr2t[j] = W_r2[m*256 + k];
        } else {
            int fi = i - S7;
            double s = 0.0, wsq = 0.0;
            for (int d = 0; d < 64; d++) {
                double u = (double)flow_u[fi*64+d], w = (double)flow_w[fi*64+d];
                s += u*w; wsq += w*w;
            }
            double sp = (s > 0.0) ? s + log1p(exp(-s)) : log1p(exp(s));
            double m = -1.0 + sp;
            double coef = m / (wsq + 1e-6);
            for (int d = 0; d < 64; d++)
                g_uhat[fi*64+d] = (double)flow_u[fi*64+d] + coef*(double)flow_w[fi*64+d];
            g_cflow[fi] = s + coef * wsq;
        }
    }
}

__device__ __forceinline__ float gelu_f(float x) {
    return 0.5f * x * (1.f + erff(x * 0.70710678118654752f));
}
__device__ __forceinline__ uint32_t smem_u32(const void* p) {
    return (uint32_t)__cvta_generic_to_shared(p);
}
#define CP_ASYNC16(d, s) asm volatile("cp.async.ca.shared.global [%0], [%1], 16;\n" :: "r"(d), "l"(s))
#define CP_COMMIT()      asm volatile("cp.async.commit_group;\n" ::: "memory")
#define CP_WAIT0()       asm volatile("cp.async.wait_group 0;\n" ::: "memory")

// packed f32x2 fma: a = x*w + a elementwise on (lo,hi) float pairs
__device__ __forceinline__ void fma2(unsigned long long& a, unsigned long long x, unsigned long long w) {
    asm("fma.rn.f32x2 %0, %1, %2, %3;" : "=l"(a) : "l"(x), "l"(w), "l"(a));
}
__device__ __forceinline__ float hsum2(unsigned long long v) {
    float lo = __uint_as_float((unsigned)(v & 0xffffffffull));
    float hi = __uint_as_float((unsigned)(v >> 32));
    return lo + hi;
}

// Small GEMM: OUT[16 x <=128] (+)= IN[16 x K] @ Wk (k-pair-interleaved, pair-row stride 256 floats).
// 4x2 microtile, FFMA2 k-pair accumulation, cp.async double-buffer, one barrier/tile.
// acc[8] u64 caller-persistent (row-major (r,c)); init zeroes, fin sums halves+bias(+GELU)+stores.
__device__ __forceinline__ void gemm_s(
    const float* smIn, int pitch, int K,
    const float* __restrict__ Wk, const float* __restrict__ bias,
    int Mreal, float* smOut, int opitch, int act, float* Wt,
    unsigned long long* acc, int init, int fin)
{
    const int tid = threadIdx.x;
    const int rg = tid >> 6;
    const int mloc = (tid & 63) << 1;
    const int srow = tid >> 5;            // pair-row 0..7
    const int scol = (tid & 31) << 2;     // float offset within pair-row
    const float* in0 = smIn + rg*4*pitch;
    const int T = K >> 4;                 // 8 pair-rows per tile
    {
        const float* src = Wk + (size_t)srow*256 + scol;
        #pragma unroll
        for (int s = 0; s < 2; s++) {
            uint32_t d = smem_u32(Wt + srow*260 + scol + s*128);
            CP_ASYNC16(d, src + s*128);
        }
        CP_COMMIT();
    }
    if (init) {
        #pragma unroll
        for (int i = 0; i < 8; i++) acc[i] = 0ull;
    }
    int buf = 0;
    for (int t = 0; t < T; t++) {
        CP_WAIT0();
        __syncthreads();            // tile t visible; tile t-1 consumers done
        if (t + 1 < T) {
            const float* src = Wk + (size_t)((t+1)*8 + srow)*256 + scol;
            float* Wd = Wt + (buf^1)*2080;
            #pragma unroll
            for (int s = 0; s < 2; s++) {
                uint32_t d = smem_u32(Wd + srow*260 + scol + s*128);
                CP_ASYNC16(d, src + s*128);
            }
            CP_COMMIT();
        }
        const float* W = Wt + buf*2080;
        const float* i0 = in0 + t*16;
        #pragma unroll
        for (int pp = 0; pp < 4; pp++) {
            ulonglong2 x0 = *(const ulonglong2*)(i0 + pp*4);
            ulonglong2 x1 = *(const ulonglong2*)(i0 + pitch + pp*4);
            ulonglong2 x2 = *(const ulonglong2*)(i0 + 2*pitch + pp*4);
            ulonglong2 x3 = *(const ulonglong2*)(i0 + 3*pitch + pp*4);
            #pragma unroll
            for (int h = 0; h < 2; h++) {
                ulonglong2 wv = *(const ulonglong2*)&W[(2*pp+h)*260 + mloc*2];
                unsigned long long p0 = h ? x0.y : x0.x;
                unsigned long long p1 = h ? x1.y : x1.x;
                unsigned long long p2 = h ? x2.y : x2.x;
                unsigned long long p3 = h ? x3.y : x3.x;
                fma2(acc[0], p0, wv.x); fma2(acc[1], p0, wv.y);
                fma2(acc[2], p1, wv.x); fma2(acc[3], p1, wv.y);
                fma2(acc[4], p2, wv.x); fma2(acc[5], p2, wv.y);
                fma2(acc[6], p3, wv.x); fma2(acc[7], p3, wv.y);
            }
        }
        buf ^= 1;
    }
    __syncthreads();               // all tile reads done (in-place store + Wt reuse safe)
    if (fin && mloc < Mreal) {
        float b0 = bias[mloc], b1 = bias[mloc+1];
        int r0 = rg*4;
        #pragma unroll
        for (int r = 0; r < 4; r++) {
            float2 o;
            o.x = hsum2(acc[2*r])   + b0;
            o.y = hsum2(acc[2*r+1]) + b1;
            if (act) { o.x = gelu_f(o.x); o.y = gelu_f(o.y); }
            *(float2*)&smOut[(size_t)(r0+r)*opitch + mloc] = o;
        }
    }
}

// Large GEMM: OUT[16 x 256] = IN[16 x K] @ Wk slice + bias, opt GELU.
// Wk k-pair-interleaved with pair-row stride wrow floats (= 2*M_full); slice via base offset.
// 8x2 microtile, FFMA2, cp.async double-buffer, one barrier/tile.
__device__ __forceinline__ void gemm_l(
    const float* smIn, int pitch, int K,
    const float* __restrict__ Wk, int wrow,
    const float* __restrict__ bias,
    float* smOut, int opitch, int act, float* Wt)
{
    const int tid = threadIdx.x;
    const int mloc = (tid & 127) << 1;
    const int rg = tid >> 7;
    const int srow = tid >> 5;            // pair-row 0..7
    const int scol = (tid & 31) << 2;
    const float* inb = smIn + rg*8*pitch;
    const int T = K >> 4;
    {
        const float* src = Wk + (size_t)srow*wrow + scol;
        #pragma unroll
        for (int s = 0; s < 4; s++) {
            uint32_t d = smem_u32(Wt + srow*516 + scol + s*128);
            CP_ASYNC16(d, src + s*128);
        }
        CP_COMMIT();
    }
    unsigned long long acc[16];
    #pragma unroll
    for (int i = 0; i < 16; i++) acc[i] = 0ull;
    int buf = 0;
    for (int t = 0; t < T; t++) {
        CP_WAIT0();
        __syncthreads();
        if (t + 1 < T) {
            const float* src = Wk + (size_t)((t+1)*8 + srow)*wrow + scol;
            float* Wd = Wt + (buf^1)*4128;
            #pragma unroll
            for (int s = 0; s < 4; s++) {
                uint32_t d = smem_u32(Wd + srow*516 + scol + s*128);
                CP_ASYNC16(d, src + s*128);
            }
            CP_COMMIT();
        }
        const float* W = Wt + buf*4128;
        const float* ix = inb + t*16;
        #pragma unroll
        for (int pp = 0; pp < 4; pp++) {
            ulonglong2 xv[8];
            #pragma unroll
            for (int r = 0; r < 8; r++)
                xv[r] = *(const ulonglong2*)(ix + r*pitch + pp*4);
            #pragma unroll
            for (int h = 0; h < 2; h++) {
                ulonglong2 wv = *(const ulonglong2*)&W[(2*pp+h)*516 + mloc*2];
                #pragma unroll
                for (int r = 0; r < 8; r++) {
                    unsigned long long xp = h ? xv[r].y : xv[r].x;
                    fma2(acc[2*r],   xp, wv.x);
                    fma2(acc[2*r+1], xp, wv.y);
                }
            }
        }
        buf ^= 1;
    }
    __syncthreads();
    float b0 = bias[mloc], b1 = bias[mloc+1];
    #pragma unroll
    for (int r = 0; r < 8; r++) {
        float2 o;
        o.x = hsum2(acc[2*r])   + b0;
        o.y = hsum2(acc[2*r+1]) + b1;
        if (act) { o.x = gelu_f(o.x); o.y = gelu_f(o.y); }
        *(float2*)&smOut[(size_t)(rg*8 + r)*opitch + mloc] = o;
    }
}

__global__ void __launch_bounds__(NT, 3) fused_kernel(
    const float* __restrict__ x_enc, const float* __restrict__ eps,
    const float* __restrict__ p_aw, const float* __restrict__ p_ab,
    const float* __restrict__ b_sc,
    const float* __restrict__ b_r1, const float* __restrict__ b_r2,
    const float* __restrict__ b_r3,
    const float* __restrict__ flow_w, const float* __restrict__ flow_b,
    float* __restrict__ out)
{
    extern __shared__ float smn[];
    float* sA    = smn + P_A;
    float* sINP  = smn + P_A;       // [z | h], pitch 192, aliases xn
    float* sPB   = smn + P_PB;
    float* sMean = smn + P_MEAN;
    float* sStd  = smn + P_STD;
    float* sScale= smn + P_SCALE;
    float* sB    = smn + P_B;
    float* sWT   = smn + P_WT;

    int tid = threadIdx.x;
    int n0 = blockIdx.x * ROWS;
    float aw = p_aw[0], ab = p_ab[0];
    int warp = tid >> 5, lane = tid & 31;
    unsigned long long acc[8];

    // ---- 1. load x (x_enc[b][l][c] -> xn_raw[r][l], n = b*7+c) ----
    for (int t = tid; t < ROWS*L; t += NT) {
        int r = t & 15, l = t >> 4;
        int n = n0 + r;
        int b = n / 7, c = n - b*7;
        sA[r*L + l] = x_enc[(b*L + l)*7 + c];
    }
    __syncthreads();

    // ---- 2. per-row mean/std ----
    #pragma unroll
    for (int rr = 0; rr < 2; rr++) {
        int r = warp*2 + rr;
        const float* row = sA + r*L;
        float s = 0.f, sq = 0.f;
        for (int l2 = lane; l2 < L; l2 += 32) { float v = row[l2]; s += v; sq += v*v; }
        #pragma unroll
        for (int o = 16; o > 0; o >>= 1) {
            s  += __shfl_xor_sync(0xffffffffu, s, o);
            sq += __shfl_xor_sync(0xffffffffu, sq, o);
        }
        if (lane == 0) {
            float mean = s * (1.f/336.f);
            float var = sq * (1.f/336.f) - mean*mean;
            float sd = sqrtf(var + 1e-5f);
            sMean[r] = mean; sStd[r] = sd; sScale[r] = aw / sd;
        }
    }
    __syncthreads();

    // ---- 3. normalize in place ----
    for (int t = tid; t < ROWS*L; t += NT) {
        int r = t / L;
        sA[t] = (sA[t] - sMean[r]) * sScale[r] + ab;
    }
    __syncthreads();

    // ---- 4. pbar[r][j] = mean over 41 patches ----
    {
        int r = tid >> 4, j = tid & 15;
        float s = 0.f;
        #pragma unroll
        for (int pp = 0; pp < 41; pp++) s += sA[r*L + pp*8 + j];
        sPB[r*16 + j] = s * (1.f/41.f);
    }
    // (gemm internal barriers order pbar/xn before reads)

    // ---- 5. shortcut = xn @ Wsc^T + b_sc  -> gmem scratch ----
    gemm_s(sA, L, L, g_Wsct, b_sc, 96, g_short + (size_t)n0*96, 96, 0, sWT, acc, 1, 1);
    // ---- 6. h = pbar @ Wc^T + bc  -> inp[:,64:192] ----
    gemm_s(sPB, 16, 16, g_Wct, g_bc, 128, sINP + 64, 192, 0, sWT, acc, 1, 1);
    // ---- 7. [mu|lv] = h @ Wml^T + bml ----
    gemm_s(sINP + 64, 192, 128, g_Wmlt, g_bml, 128, sB, 128, 0, sWT, acc, 1, 1);
    __syncthreads();

    // ---- 8+9. reparam (FP64) + planar flows (FP64 scalar chain) ----
    #pragma unroll
    for (int rr = 0; rr < 2; rr++) {
        int r = warp + rr*8;
        int n = n0 + r;
        float mu0 = sB[r*128 + lane];
        float mu1 = sB[r*128 + 32 + lane];
        float lv0 = sB[r*128 + 64 + lane];
        float lv1 = sB[r*128 + 96 + lane];
        out[OFF_MU + n*64 + lane]      = mu0;
        out[OFF_MU + n*64 + 32 + lane] = mu1;
        out[OFF_LV + n*64 + lane]      = lv0;
        out[OFF_LV + n*64 + 32 + lane] = lv1;
        double z0 = (double)mu0 + (double)eps[n*64 + lane]      * exp(0.5 * (double)lv0);
        double z1 = (double)mu1 + (double)eps[n*64 + 32 + lane] * exp(0.5 * (double)lv1);
        double ld = 0.0;
        #pragma unroll
        for (int i = 0; i < 8; i++) {
            double w0 = (double)flow_w[i*64 + lane];
            double w1 = (double)flow_w[i*64 + 32 + lane];
            double dot = z0*w0 + z1*w1;
            #pragma unroll
            for (int o = 16; o > 0; o >>= 1) dot += __shfl_xor_sync(0xffffffffu, dot, o);
            double th = tanh(dot + (double)flow_b[i]);
            z0 += th * g_uhat[i*64 + lane];
            z1 += th * g_uhat[i*64 + 32 + lane];
            ld += log(fabs(1.0 + (1.0 - th*th) * g_cflow[i]) + 1e-6);
        }
        sINP[r*192 + lane]      = (float)z0;
        sINP[r*192 + 32 + lane] = (float)z1;
        if (lane == 0) out[OFF_LD + n] = (float)ld;
    }
    // (flows write sINP/read sB; r1's first internal barrier orders)

    // ---- 10. r1 = gelu(inp @ Wr1^T + br1) -> sB ----
    gemm_l(sINP, 192, 192, g_Wr1t, 512, b_r1, sB, 256, 1, sWT);

    // ---- 11+12. r2 (2 chunks of 256) fused with r3 accumulation ----
    {
        unsigned long long acc3[8];
        #pragma unroll
        for (int c = 0; c < 2; c++) {
            // r2 chunk: output cols 256c..256c+256 -> gelu -> sA[16][256]
            gemm_l(sB, 256, 256, g_Wr2t + 512*c, 1024, b_r2 + 256*c, sA, 256, 1, sWT);
            // r3 partial: acc3 += r2chunk @ Wr3t k-slice [256c..256c+256)
            gemm_s(sA, 256, 256, g_Wr3t + (size_t)(256*c)*128, b_r3, 96,
                   sA, 96, 0, sWT, acc3, c == 0, c == 1);
        }
    }
    __syncthreads();

    // ---- 13. denorm + scatter out[b][p][c] (recon in sA[16][96]) ----
    float inv_aw = 1.f / (aw + 1e-10f);
    for (int t = tid; t < ROWS*96; t += NT) {
        int r = t & 15, pcol = t >> 4;
        int n = n0 + r;
        float v = sA[r*96 + pcol] + g_short[(size_t)n*96 + pcol];
        float den = fmaf((v - ab) * inv_aw, sStd[r], sMean[r]);
        int b = n/7, c = n - b*7;
        out[(b*96 + pcol)*7 + c] = den;
    }
}

extern "C" void kernel_launch(void* const* d_in, const int* in_sizes, int n_in,
                              void* d_out, int out_size) {
    const float* x_enc  = (const float*)d_in[0];
    const float* eps    = (const float*)d_in[1];
    const float* aw     = (const float*)d_in[2];
    const float* ab     = (const float*)d_in[3];
    const float* W_sc   = (const float*)d_in[4];
    const float* b_sc   = (const float*)d_in[5];
    const float* W_ts   = (const float*)d_in[6];
    const float* b_ts   = (const float*)d_in[7];
    const float* W_fu   = (const float*)d_in[8];
    const float* b_fu   = (const float*)d_in[9];
    const float* W_mu   = (const float*)d_in[10];
    const float* b_mu   = (const float*)d_in[11];
    const float* W_lv   = (const float*)d_in[12];
    const float* b_lv   = (const float*)d_in[13];
    const float* flow_u = (const float*)d_in[14];
    const float* flow_w = (const float*)d_in[15];
    const float* flow_b = (const float*)d_in[16];
    const float* W_r1   = (const float*)d_in[17];
    const float* b_r1   = (const float*)d_in[18];
    const float* W_r2   = (const float*)d_in[19];
    const float* b_r2   = (const float*)d_in[20];
    const float* W_r3   = (const float*)d_in[21];
    const float* b_r3   = (const float*)d_in[22];
    float* out = (float*)d_out;

    cudaFuncSetAttribute(fused_kernel, cudaFuncAttributeMaxDynamicSharedMemorySize, SMEM_BYTES);

    prep_kernel<<<128, 256>>>(W_sc, W_mu, b_mu, W_lv, b_lv, W_r3,
                              W_fu, b_fu, W_ts, b_ts, flow_u, flow_w, W_r1, W_r2);
    fused_kernel<<<448, NT, SMEM_BYTES>>>(x_enc, eps, aw, ab, b_sc,
                                          b_r1, b_r2, b_r3,
                                          flow_w, flow_b, out);
}

// round 10
// speedup vs baseline: 1.1938x; 1.1938x over previous
#include <cuda_runtime.h>
#include <math.h>
#include <stdint.h>

#define NT 256
#define ROWS 16
#define L 336
#define OFF_MU (1024*96*7)
#define OFF_LV (OFF_MU + 7168*64)
#define OFF_LD (OFF_LV + 7168*64)

// smem pool (floats)
#define P_A     0        // xn[16][336]; aliases: sINP[16][196], r2chunk[16][260], recon[16][100]
#define P_PB    5376     // pbar[16][16]
#define P_MEAN  5632
#define P_STD   5648
#define P_SCALE 5664
#define P_B     5680     // ml/r1 out [16][260] = 4160
#define P_WT    9840     // weight tiles: mma 2 x 16 x 264 = 8448 (FFMA uses 2 x 16 x 132 subset)
#define SMEM_FLOATS 18288
#define SMEM_BYTES (SMEM_FLOATS*4)

#define PITCH_INP 196    // ≡4 mod 32: conflict-free mma A-frag loads
#define PITCH_B   260    // ≡4 mod 32

// k-major weights [k][m]
__device__ __align__(16) float g_Wsct[336*128];   // m padded 96->128
__device__ __align__(16) float g_Wr3t[512*128];
__device__ __align__(16) float g_Wmlt[128*128];   // [mu|lv]
__device__ __align__(16) float g_bml[128];
__device__ __align__(16) float g_Wct[16*128];
__device__ __align__(16) float g_bc[128];
__device__ __align__(16) float g_Wr1t[192*256];
__device__ __align__(16) float g_Wr2t[256*512];
__device__ double g_uhat[8*64];
__device__ double g_cflow[8];
__device__ __align__(16) float g_short[7168*96];

__global__ void prep_kernel(const float* __restrict__ W_sc,
                            const float* __restrict__ W_mu, const float* __restrict__ b_mu,
                            const float* __restrict__ W_lv, const float* __restrict__ b_lv,
                            const float* __restrict__ W_r3,
                            const float* __restrict__ W_fu, const float* __restrict__ b_fu,
                            const float* __restrict__ W_ts, const float* __restrict__ b_ts,
                            const float* __restrict__ flow_u, const float* __restrict__ flow_w,
                            const float* __restrict__ W_r1, const float* __restrict__ W_r2)
{
    int idx = blockIdx.x * blockDim.x + threadIdx.x;
    int stride = gridDim.x * blockDim.x;
    const int S0 = 336*128;
    const int S1 = S0 + 512*128;
    const int S2 = S1 + 128*128;
    const int S3 = S2 + 128;
    const int S4 = S3 + 16*128;
    const int S5 = S4 + 128;
    const int S6 = S5 + 192*256;
    const int S7 = S6 + 256*512;
    const int S8 = S7 + 8;
    for (int i = idx; i < S8; i += stride) {
        if (i < S0) {
            int k = i >> 7, m = i & 127;
            g_Wsct[i] = (m < 96) ? W_sc[m*336 + k] : 0.f;
        } else if (i < S1) {
            int j = i - S0;
            int k = j >> 7, m = j & 127;
            g_Wr3t[j] = (m < 96) ? W_r3[m*512 + k] : 0.f;
        } else if (i < S2) {
            int j = i - S1;
            int k = j >> 7, m = j & 127;
            g_Wmlt[j] = (m < 64) ? W_mu[m*128 + k] : W_lv[(m-64)*128 + k];
        } else if (i < S3) {
            int j = i - S2;
            g_bml[j] = (j < 64) ? b_mu[j] : b_lv[j-64];
        } else if (i < S4) {
            int j = i - S3;
            int l = j >> 7, h = j & 127;
            float s = 0.f;
            for (int d = 0; d < 128; d++) s += W_fu[h*256 + d] * W_ts[d*16 + l];
            g_Wct[j] = s;
        } else if (i < S5) {
            int h = i - S4;
            float s = 0.f;
            for (int d = 0; d < 128; d++) s += W_fu[h*256 + d] * b_ts[d];
            g_bc[h] = s + b_fu[h];
        } else if (i < S6) {
            int j = i - S5;
            int k = j >> 8, m = j & 255;
            g_Wr1t[j] = W_r1[m*192 + k];
        } else if (i < S7) {
            int j = i - S6;
            int k = j >> 9, m = j & 511;
            g_Wr2t[j] = W_r2[m*256 + k];
        } else {
            int fi = i - S7;
            double s = 0.0, wsq = 0.0;
            for (int d = 0; d < 64; d++) {
                double u = (double)flow_u[fi*64+d], w = (double)flow_w[fi*64+d];
                s += u*w; wsq += w*w;
            }
            double sp = (s > 0.0) ? s + log1p(exp(-s)) : log1p(exp(s));
            double m = -1.0 + sp;
            double coef = m / (wsq + 1e-6);
            for (int d = 0; d < 64; d++)
                g_uhat[fi*64+d] = (double)flow_u[fi*64+d] + coef*(double)flow_w[fi*64+d];
            g_cflow[fi] = s + coef * wsq;
        }
    }
}

__device__ __forceinline__ float gelu_f(float x) {
    return 0.5f * x * (1.f + erff(x * 0.70710678118654752f));
}
__device__ __forceinline__ uint32_t smem_u32(const void* p) {
    return (uint32_t)__cvta_generic_to_shared(p);
}
__device__ __forceinline__ uint32_t f2tf(float x) {
    uint32_t r; asm("cvt.rna.tf32.f32 %0, %1;" : "=r"(r) : "f"(x)); return r;
}
#define CP_ASYNC16(d, s) asm volatile("cp.async.ca.shared.global [%0], [%1], 16;\n" :: "r"(d), "l"(s))
#define CP_COMMIT()      asm volatile("cp.async.commit_group;\n" ::: "memory")
#define CP_WAIT0()       asm volatile("cp.async.wait_group 0;\n" ::: "memory")

#define MMA_TF32(c, a0,a1,a2,a3, b0,b1) \
    asm volatile("mma.sync.aligned.m16n8k8.row.col.f32.tf32.tf32.f32 " \
        "{%0,%1,%2,%3}, {%4,%5,%6,%7}, {%8,%9}, {%0,%1,%2,%3};" \
        : "+f"((c)[0]), "+f"((c)[1]), "+f"((c)[2]), "+f"((c)[3]) \
        : "r"(a0), "r"(a1), "r"(a2), "r"(a3), "r"(b0), "r"(b1))

// ---------------- FFMA fp32 GEMM (R7-proven, bit-exact path) ----------------
// OUT[16 x <=128] (+)= IN[16 x K] @ Wk (k-major, row stride 128). 4x2 microtile,
// KT=16, cp.async double-buffer, one barrier per tile.
__device__ __forceinline__ void gemm_s(
    const float* smIn, int pitch, int K,
    const float* __restrict__ Wk, const float* __restrict__ bias,
    int Mreal, float* smOut, int opitch, int act, float* Wt,
    float* acc, int init, int fin)
{
    const int tid = threadIdx.x;
    const int rg = tid >> 6;
    const int mloc = (tid & 63) << 1;
    const int srow = tid >> 5;
    const int scol = (tid & 31) << 2;
    const float* in0 = smIn + rg*4*pitch;
    const int T = K >> 4;
    {
        #pragma unroll
        for (int s2 = 0; s2 < 2; s2++) {
            uint32_t d = smem_u32(Wt + (srow + 8*s2)*132 + scol);
            CP_ASYNC16(d, Wk + (size_t)(srow + 8*s2)*128 + scol);
        }
        CP_COMMIT();
    }
    if (init) {
        #pragma unroll
        for (int i = 0; i < 8; i++) acc[i] = 0.f;
    }
    int buf = 0;
    for (int t = 0; t < T; t++) {
        CP_WAIT0();
        __syncthreads();
        if (t + 1 < T) {
            const float* g = Wk + (size_t)((t+1)*16)*128;
            float* Wd = Wt + (buf^1)*2112;
            #pragma unroll
            for (int s2 = 0; s2 < 2; s2++) {
                uint32_t d = smem_u32(Wd + (srow + 8*s2)*132 + scol);
                CP_ASYNC16(d, g + (size_t)(srow + 8*s2)*128 + scol);
            }
            CP_COMMIT();
        }
        const float* W = Wt + buf*2112;
        const float* i0 = in0 + t*16;
        #pragma unroll
        for (int kk = 0; kk < 16; kk += 2) {
            float2 w0 = *(const float2*)&W[kk*132 + mloc];
            float2 w1 = *(const float2*)&W[(kk+1)*132 + mloc];
            float2 x0 = *(const float2*)(i0 + kk);
            float2 x1 = *(const float2*)(i0 + pitch + kk);
            float2 x2 = *(const float2*)(i0 + 2*pitch + kk);
            float2 x3 = *(const float2*)(i0 + 3*pitch + kk);
            acc[0] = fmaf(x0.x, w0.x, acc[0]); acc[0] = fmaf(x0.y, w1.x, acc[0]);
            acc[1] = fmaf(x0.x, w0.y, acc[1]); acc[1] = fmaf(x0.y, w1.y, acc[1]);
            acc[2] = fmaf(x1.x, w0.x, acc[2]); acc[2] = fmaf(x1.y, w1.x, acc[2]);
            acc[3] = fmaf(x1.x, w0.y, acc[3]); acc[3] = fmaf(x1.y, w1.y, acc[3]);
            acc[4] = fmaf(x2.x, w0.x, acc[4]); acc[4] = fmaf(x2.y, w1.x, acc[4]);
            acc[5] = fmaf(x2.x, w0.y, acc[5]); acc[5] = fmaf(x2.y, w1.y, acc[5]);
            acc[6] = fmaf(x3.x, w0.x, acc[6]); acc[6] = fmaf(x3.y, w1.x, acc[6]);
            acc[7] = fmaf(x3.x, w0.y, acc[7]); acc[7] = fmaf(x3.y, w1.y, acc[7]);
        }
        buf ^= 1;
    }
    __syncthreads();
    if (fin && mloc < Mreal) {
        float b0 = bias[mloc], b1 = bias[mloc+1];
        int r0 = rg*4;
        #pragma unroll
        for (int r = 0; r < 4; r++) {
            float2 o;
            o.x = acc[2*r]   + b0;
            o.y = acc[2*r+1] + b1;
            if (act) { o.x = gelu_f(o.x); o.y = gelu_f(o.y); }
            *(float2*)&smOut[(size_t)(r0+r)*opitch + mloc] = o;
        }
    }
}

// ---------------- 3xTF32 tensor-core GEMM ----------------
// OUT[16 x M] (+)= IN[16 x K] @ Wk (k-major [k][m], row stride wstride).
// M = 64*NTILES (256 or 128). Warp w owns cols [w*8*NTILES, +8*NTILES).
// A split hi/lo in regs (cvt.rna.tf32); 3 mma per (n-tile, k8): ahi*bhi + ahi*blo + alo*bhi.
// C[4*NTILES] caller-persistent; init zeroes, fin adds bias(+GELU)+stores (warps < nws only).
template<int NTILES>
__device__ __forceinline__ void gemm_mma(
    const float* smIn, int pitch, int K,
    const float* __restrict__ Wk, int wstride,
    const float* __restrict__ bias,
    float* smOut, int opitch, int act, float* Wt,
    float* C, int init, int fin, int nws)
{
    constexpr int TP  = (NTILES == 4) ? 264 : 136;   // tile pitch (≡8 mod 32: B-frags conflict-free)
    constexpr int BUF = 16*TP;
    const int tid = threadIdx.x;
    const int lane = tid & 31;
    const int warp = tid >> 5;
    const int g = lane >> 2, t4 = lane & 3;
    const int n0w = warp * (8*NTILES);
    const int T = K >> 4;
    const int srow  = (NTILES == 4) ? (tid >> 6) : (tid >> 5);
    const int sstep = (NTILES == 4) ? 4 : 8;
    const int scol  = ((NTILES == 4) ? (tid & 63) : (tid & 31)) << 2;
    constexpr int SITER = (NTILES == 4) ? 4 : 2;
    {
        #pragma unroll
        for (int s = 0; s < SITER; s++) {
            uint32_t d = smem_u32(Wt + (srow + sstep*s)*TP + scol);
            CP_ASYNC16(d, Wk + (size_t)(srow + sstep*s)*wstride + scol);
        }
        CP_COMMIT();
    }
    if (init) {
        #pragma unroll
        for (int i = 0; i < 4*NTILES; i++) C[i] = 0.f;
    }
    int buf = 0;
    for (int t = 0; t < T; t++) {
        CP_WAIT0();
        __syncthreads();
        if (t + 1 < T) {
            const float* gsrc = Wk + (size_t)((t+1)*16)*wstride;
            float* Wd = Wt + (buf^1)*BUF;
            #pragma unroll
            for (int s = 0; s < SITER; s++) {
                uint32_t d = smem_u32(Wd + (srow + sstep*s)*TP + scol);
                CP_ASYNC16(d, gsrc + (size_t)(srow + sstep*s)*wstride + scol);
            }
            CP_COMMIT();
        }
        const float* W = Wt + buf*BUF;
        #pragma unroll
        for (int kk = 0; kk < 16; kk += 8) {
            const float* ia = smIn + t*16 + kk;
            float ar0 = ia[g*pitch + t4];
            float ar1 = ia[(g+8)*pitch + t4];
            float ar2 = ia[g*pitch + t4 + 4];
            float ar3 = ia[(g+8)*pitch + t4 + 4];
            uint32_t ah0 = f2tf(ar0), ah1 = f2tf(ar1), ah2 = f2tf(ar2), ah3 = f2tf(ar3);
            uint32_t al0 = f2tf(ar0 - __uint_as_float(ah0));
            uint32_t al1 = f2tf(ar1 - __uint_as_float(ah1));
            uint32_t al2 = f2tf(ar2 - __uint_as_float(ah2));
            uint32_t al3 = f2tf(ar3 - __uint_as_float(ah3));
            const float* Wkk = W + kk*TP;
            #pragma unroll
            for (int nt = 0; nt < NTILES; nt++) {
                int n = n0w + nt*8 + g;
                float br0 = Wkk[t4*TP + n];
                float br1 = Wkk[(t4+4)*TP + n];
                uint32_t bh0 = f2tf(br0), bh1 = f2tf(br1);
                uint32_t bl0 = f2tf(br0 - __uint_as_float(bh0));
                uint32_t bl1 = f2tf(br1 - __uint_as_float(bh1));
                float* c = C + nt*4;
                MMA_TF32(c, ah0, ah1, ah2, ah3, bh0, bh1);
                MMA_TF32(c, ah0, ah1, ah2, ah3, bl0, bl1);
                MMA_TF32(c, al0, al1, al2, al3, bh0, bh1);
            }
        }
        buf ^= 1;
    }
    __syncthreads();
    if (fin && warp < nws) {
        #pragma unroll
        for (int nt = 0; nt < NTILES; nt++) {
            int col = n0w + nt*8 + 2*t4;
            float2 bb = *(const float2*)&bias[col];
            float2 o;
            o.x = C[nt*4+0] + bb.x; o.y = C[nt*4+1] + bb.y;
            if (act) { o.x = gelu_f(o.x); o.y = gelu_f(o.y); }
            *(float2*)&smOut[(size_t)g*opitch + col] = o;
            o.x = C[nt*4+2] + bb.x; o.y = C[nt*4+3] + bb.y;
            if (act) { o.x = gelu_f(o.x); o.y = gelu_f(o.y); }
            *(float2*)&smOut[(size_t)(g+8)*opitch + col] = o;
        }
    }
}

__global__ void __launch_bounds__(NT, 3) fused_kernel(
    const float* __restrict__ x_enc, const float* __restrict__ eps,
    const float* __restrict__ p_aw, const float* __restrict__ p_ab,
    const float* __restrict__ b_sc,
    const float* __restrict__ b_r1, const float* __restrict__ b_r2,
    const float* __restrict__ b_r3,
    const float* __restrict__ flow_w, const float* __restrict__ flow_b,
    float* __restrict__ out)
{
    extern __shared__ float smn[];
    float* sA    = smn + P_A;       // xn (pitch 336) / sINP (196) / r2chunk (260) / recon (100)
    float* sINP  = smn + P_A;
    float* sPB   = smn + P_PB;
    float* sMean = smn + P_MEAN;
    float* sStd  = smn + P_STD;
    float* sScale= smn + P_SCALE;
    float* sB    = smn + P_B;       // pitch 260
    float* sWT   = smn + P_WT;

    int tid = threadIdx.x;
    int n0 = blockIdx.x * ROWS;
    float aw = p_aw[0], ab = p_ab[0];
    int warp = tid >> 5, lane = tid & 31;
    float acc[8];

    // ---- 1. load x ----
    for (int t = tid; t < ROWS*L; t += NT) {
        int r = t & 15, l = t >> 4;
        int n = n0 + r;
        int b = n / 7, c = n - b*7;
        sA[r*L + l] = x_enc[(b*L + l)*7 + c];
    }
    __syncthreads();

    // ---- 2. per-row mean/std ----
    #pragma unroll
    for (int rr = 0; rr < 2; rr++) {
        int r = warp*2 + rr;
        const float* row = sA + r*L;
        float s = 0.f, sq = 0.f;
        for (int l2 = lane; l2 < L; l2 += 32) { float v = row[l2]; s += v; sq += v*v; }
        #pragma unroll
        for (int o = 16; o > 0; o >>= 1) {
            s  += __shfl_xor_sync(0xffffffffu, s, o);
            sq += __shfl_xor_sync(0xffffffffu, sq, o);
        }
        if (lane == 0) {
            float mean = s * (1.f/336.f);
            float var = sq * (1.f/336.f) - mean*mean;
            float sd = sqrtf(var + 1e-5f);
            sMean[r] = mean; sStd[r] = sd; sScale[r] = aw / sd;
        }
    }
    __syncthreads();

    // ---- 3. normalize ----
    for (int t = tid; t < ROWS*L; t += NT) {
        int r = t / L;
        sA[t] = (sA[t] - sMean[r]) * sScale[r] + ab;
    }
    __syncthreads();

    // ---- 4. pbar ----
    {
        int r = tid >> 4, j = tid & 15;
        float s = 0.f;
        #pragma unroll
        for (int pp = 0; pp < 41; pp++) s += sA[r*L + pp*8 + j];
        sPB[r*16 + j] = s * (1.f/41.f);
    }
    // (gemm internal barriers order pbar/xn before reads)

    // ---- 5. shortcut (FFMA exact) -> gmem scratch ----
    gemm_s(sA, L, L, g_Wsct, b_sc, 96, g_short + (size_t)n0*96, 96, 0, sWT, acc, 1, 1);
    // ---- 6. h (FFMA exact) -> sINP[:,64:192] ----
    gemm_s(sPB, 16, 16, g_Wct, g_bc, 128, sINP + 64, PITCH_INP, 0, sWT, acc, 1, 1);
    // ---- 7. [mu|lv] (FFMA exact) -> sB ----
    gemm_s(sINP + 64, PITCH_INP, 128, g_Wmlt, g_bml, 128, sB, PITCH_B, 0, sWT, acc, 1, 1);
    __syncthreads();

    // ---- 8+9. reparam + flows (FP64, bit-identical to baseline) ----
    #pragma unroll
    for (int rr = 0; rr < 2; rr++) {
        int r = warp + rr*8;
        int n = n0 + r;
        float mu0 = sB[r*PITCH_B + lane];
        float mu1 = sB[r*PITCH_B + 32 + lane];
        float lv0 = sB[r*PITCH_B + 64 + lane];
        float lv1 = sB[r*PITCH_B + 96 + lane];
        out[OFF_MU + n*64 + lane]      = mu0;
        out[OFF_MU + n*64 + 32 + lane] = mu1;
        out[OFF_LV + n*64 + lane]      = lv0;
        out[OFF_LV + n*64 + 32 + lane] = lv1;
        double z0 = (double)mu0 + (double)eps[n*64 + lane]      * exp(0.5 * (double)lv0);
        double z1 = (double)mu1 + (double)eps[n*64 + 32 + lane] * exp(0.5 * (double)lv1);
        double ld = 0.0;
        #pragma unroll
        for (int i = 0; i < 8; i++) {
            double w0 = (double)flow_w[i*64 + lane];
            double w1 = (double)flow_w[i*64 + 32 + lane];
            double dot = z0*w0 + z1*w1;
            #pragma unroll
            for (int o = 16; o > 0; o >>= 1) dot += __shfl_xor_sync(0xffffffffu, dot, o);
            double th = tanh(dot + (double)flow_b[i]);
            z0 += th * g_uhat[i*64 + lane];
            z1 += th * g_uhat[i*64 + 32 + lane];
            ld += log(fabs(1.0 + (1.0 - th*th) * g_cflow[i]) + 1e-6);
        }
        sINP[r*PITCH_INP + lane]      = (float)z0;
        sINP[r*PITCH_INP + 32 + lane] = (float)z1;
        if (lane == 0) out[OFF_LD + n] = (float)ld;
    }
    // (flows write sINP; gemm's first internal barrier orders before A reads)

    // ---- 10. r1 (3xTF32 mma) -> sB ----
    {
        float C1[16];
        gemm_mma<4>(sINP, PITCH_INP, 192, g_Wr1t, 256, b_r1, sB, PITCH_B, 1, sWT, C1, 1, 1, 8);
    }
    // ---- 11+12. r2 chunks (mma) fused with r3 accumulation (mma, C persists) ----
    {
        float C3[8];
        #pragma unroll
        for (int c = 0; c < 2; c++) {
            float C2[16];
            gemm_mma<4>(sB, PITCH_B, 256, g_Wr2t + 256*c, 512, b_r2 + 256*c,
                        sA, PITCH_B, 1, sWT, C2, 1, 1, 8);
            gemm_mma<2>(sA, PITCH_B, 256, g_Wr3t + (size_t)(256*c)*128, 128, b_r3,
                        sA, 100, 0, sWT, C3, c == 0, c == 1, 6);
        }
    }
    __syncthreads();

    // ---- 13. denorm + scatter (recon in sA pitch 100) ----
    float inv_aw = 1.f / (aw + 1e-10f);
    for (int t = tid; t < ROWS*96; t += NT) {
        int r = t & 15, pcol = t >> 4;
        int n = n0 + r;
        float v = sA[r*100 + pcol] + g_short[(size_t)n*96 + pcol];
        float den = fmaf((v - ab) * inv_aw, sStd[r], sMean[r]);
        int b = n/7, c = n - b*7;
        out[(b*96 + pcol)*7 + c] = den;
    }
}

extern "C" void kernel_launch(void* const* d_in, const int* in_sizes, int n_in,
                              void* d_out, int out_size) {
    const float* x_enc  = (const float*)d_in[0];
    const float* eps    = (const float*)d_in[1];
    const float* aw     = (const float*)d_in[2];
    const float* ab     = (const float*)d_in[3];
    const float* W_sc   = (const float*)d_in[4];
    const float* b_sc   = (const float*)d_in[5];
    const float* W_ts   = (const float*)d_in[6];
    const float* b_ts   = (const float*)d_in[7];
    const float* W_fu   = (const float*)d_in[8];
    const float* b_fu   = (const float*)d_in[9];
    const float* W_mu   = (const float*)d_in[10];
    const float* b_mu   = (const float*)d_in[11];
    const float* W_lv   = (const float*)d_in[12];
    const float* b_lv   = (const float*)d_in[13];
    const float* flow_u = (const float*)d_in[14];
    const float* flow_w = (const float*)d_in[15];
    const float* flow_b = (const float*)d_in[16];
    const float* W_r1   = (const float*)d_in[17];
    const float* b_r1   = (const float*)d_in[18];
    const float* W_r2   = (const float*)d_in[19];
    const float* b_r2   = (const float*)d_in[20];
    const float* W_r3   = (const float*)d_in[21];
    const float* b_r3   = (const float*)d_in[22];
    float* out = (float*)d_out;

    cudaFuncSetAttribute(fused_kernel, cudaFuncAttributeMaxDynamicSharedMemorySize, SMEM_BYTES);

    prep_kernel<<<128, 256>>>(W_sc, W_mu, b_mu, W_lv, b_lv, W_r3,
                              W_fu, b_fu, W_ts, b_ts, flow_u, flow_w, W_r1, W_r2);
    fused_kernel<<<448, NT, SMEM_BYTES>>>(x_enc, eps, aw, ab, b_sc,
                                          b_r1, b_r2, b_r3,
                                          flow_w, flow_b, out);
}